// round 9
// baseline (speedup 1.0000x reference)
#include <cuda_runtime.h>
#include <cuda_fp16.h>
#include <math.h>
#include <stdint.h>

#define T_TOK 8192
#define HID   7168
#define NEXP  256

// scratch: sigmoid scores [T_TOK, NEXP] (8 MB)
__device__ float g_scores[(size_t)T_TOK * NEXP];
__device__ int   g_nflag;
__device__ int   g_flags[T_TOK];

#define THETA   2e-5f
#define MARG_T  (3.0f * THETA)   // score-level margins
#define MARG_G  (8.0f * THETA)   // group-sum margins

// ============================ helpers ============================
// d += a * b  (m16n8k16 f16 inputs, f32 accum)
#define MMAH(d, a, b) asm volatile( \
    "mma.sync.aligned.m16n8k16.row.col.f32.f16.f16.f32 " \
    "{%0,%1,%2,%3}, {%4,%5,%6,%7}, {%8,%9}, {%0,%1,%2,%3};" \
    : "+f"((d)[0]), "+f"((d)[1]), "+f"((d)[2]), "+f"((d)[3]) \
    : "r"((a)[0]), "r"((a)[1]), "r"((a)[2]), "r"((a)[3]), \
      "r"((b)[0]), "r"((b)[1]))

// split f32 -> (hi, lo) fp16 halves, both round-to-nearest
__device__ __forceinline__ void splitH(float f, __half& h, __half& l) {
    h = __float2half_rn(f);
    l = __float2half_rn(f - __half2float(h));
}
// pack two halves into a u32 (lo half = first element)
__device__ __forceinline__ uint32_t pack_h2(__half a, __half b) {
    __half2 h2 = __halves2half2(a, b);
    __half2_raw r = *reinterpret_cast<__half2_raw*>(&h2);
    return (uint32_t)r.x | ((uint32_t)r.y << 16);
}

// ============================ K1 config ============================
constexpr int BM = 128, BN = 128, BK = 32;
constexpr int NCHUNK = HID / BK;            // 224
constexpr int RS = 20;                      // u32 row stride (16 half2 + 4 pad)
constexpr int TILE_U  = 128 * RS;           // 2560 u32 per half-tile
constexpr int STAGE_U = 4 * TILE_U;         // Ah Al Bh Bl
constexpr int NSTAGE  = 3;
constexpr int SMEM_BYTES = NSTAGE * STAGE_U * 4;   // 122880

// ============================================================================
// K1: approx scores = sigmoid(x @ W^T), fp16 2-split, 3 MMA passes
// ============================================================================
__global__ __launch_bounds__(256, 1) void gemm_f16x2_kernel(
    const float* __restrict__ x, const float* __restrict__ w)
{
    extern __shared__ uint32_t smem[];

    const int tid  = threadIdx.x;
    const int lane = tid & 31;
    const int wid  = tid >> 5;
    const int g    = lane >> 2;
    const int tg   = lane & 3;

    const int n0 = (blockIdx.x & 1) * BN;
    const int m0 = (blockIdx.x >> 1) * BM;
    const int wm = (wid & 1) * 64;
    const int wn = (wid >> 1) * 32;

    const int lrow  = tid >> 1;
    const int lhalf = (tid & 1) * 16;
    const float* ga = x + (size_t)(m0 + lrow) * HID + lhalf;
    const float* gb = w + (size_t)(n0 + lrow) * HID + lhalf;

    float4 pa[4], pb[4];
#pragma unroll
    for (int q = 0; q < 4; ++q) {
        pa[q] = *(const float4*)(ga + q * 4);
        pb[q] = *(const float4*)(gb + q * 4);
    }

    float acc[4][4][4];
#pragma unroll
    for (int i = 0; i < 4; ++i)
#pragma unroll
        for (int j = 0; j < 4; ++j)
#pragma unroll
            for (int e = 0; e < 4; ++e) acc[i][j][e] = 0.f;

    const int wbase = lrow * RS + lhalf / 2;   // u32 index inside a half-tile

#pragma unroll 1
    for (int c = 0; c < NCHUNK; ++c) {
        const int s = c % NSTAGE;
        uint32_t* Ah = smem + s * STAGE_U;
        uint32_t* Al = Ah + TILE_U;
        uint32_t* Bh = Ah + 2 * TILE_U;
        uint32_t* Bl = Ah + 3 * TILE_U;

        // convert + store this chunk's registers
#pragma unroll
        for (int q = 0; q < 4; ++q) {
            __half h0, h1, h2, h3, l0, l1, l2, l3;
            splitH(pa[q].x, h0, l0); splitH(pa[q].y, h1, l1);
            splitH(pa[q].z, h2, l2); splitH(pa[q].w, h3, l3);
            Ah[wbase + q * 2 + 0] = pack_h2(h0, h1);
            Ah[wbase + q * 2 + 1] = pack_h2(h2, h3);
            Al[wbase + q * 2 + 0] = pack_h2(l0, l1);
            Al[wbase + q * 2 + 1] = pack_h2(l2, l3);
            splitH(pb[q].x, h0, l0); splitH(pb[q].y, h1, l1);
            splitH(pb[q].z, h2, l2); splitH(pb[q].w, h3, l3);
            Bh[wbase + q * 2 + 0] = pack_h2(h0, h1);
            Bh[wbase + q * 2 + 1] = pack_h2(h2, h3);
            Bl[wbase + q * 2 + 0] = pack_h2(l0, l1);
            Bl[wbase + q * 2 + 1] = pack_h2(l2, l3);
        }
        __syncthreads();

        // prefetch next chunk
        if (c + 1 < NCHUNK) {
            const float* na = ga + (c + 1) * BK;
            const float* nb = gb + (c + 1) * BK;
#pragma unroll
            for (int q = 0; q < 4; ++q) {
                pa[q] = *(const float4*)(na + q * 4);
                pb[q] = *(const float4*)(nb + q * 4);
            }
        }

        // MMAs on this stage
#pragma unroll
        for (int kk = 0; kk < 2; ++kk) {
            const int kb = kk * 8 + tg;
            uint32_t ah[4][4], al[4][4], bh[4][2], bl[4][2];
#pragma unroll
            for (int i = 0; i < 4; ++i) {
                const int r0 = (wm + i * 16 + g) * RS;
                const int r1 = (wm + i * 16 + g + 8) * RS;
                ah[i][0] = Ah[r0 + kb];     ah[i][1] = Ah[r1 + kb];
                ah[i][2] = Ah[r0 + kb + 4]; ah[i][3] = Ah[r1 + kb + 4];
                al[i][0] = Al[r0 + kb];     al[i][1] = Al[r1 + kb];
                al[i][2] = Al[r0 + kb + 4]; al[i][3] = Al[r1 + kb + 4];
            }
#pragma unroll
            for (int j = 0; j < 4; ++j) {
                const int rn = (wn + j * 8 + g) * RS;
                bh[j][0] = Bh[rn + kb]; bh[j][1] = Bh[rn + kb + 4];
                bl[j][0] = Bl[rn + kb]; bl[j][1] = Bl[rn + kb + 4];
            }
#pragma unroll
            for (int i = 0; i < 4; ++i)
#pragma unroll
                for (int j = 0; j < 4; ++j) {
                    MMAH(acc[i][j], ah[i], bh[j]);
                    MMAH(acc[i][j], ah[i], bl[j]);
                    MMAH(acc[i][j], al[i], bh[j]);
                }
        }
        // next iteration's STS targets a different stage; the sync above plus
        // 3-stage rotation guarantees no WAR on compute of stage s.
    }

    // epilogue: sigmoid + store
#pragma unroll
    for (int i = 0; i < 4; ++i) {
        const int r0 = m0 + wm + i * 16 + g;
#pragma unroll
        for (int j = 0; j < 4; ++j) {
            float* p0 = g_scores + (size_t)r0 * NEXP + n0 + wn + j * 8 + tg * 2;
            float* p1 = p0 + 8 * NEXP;
            float2 v0, v1;
            v0.x = 1.f / (1.f + expf(-acc[i][j][0]));
            v0.y = 1.f / (1.f + expf(-acc[i][j][1]));
            v1.x = 1.f / (1.f + expf(-acc[i][j][2]));
            v1.y = 1.f / (1.f + expf(-acc[i][j][3]));
            *(float2*)p0 = v0;
            *(float2*)p1 = v1;
        }
    }
}

// ============================================================================
// reset kernel
// ============================================================================
__global__ void reset_kernel() { g_nflag = 0; }

// ============================================================================
// K2: gate on approx scores with margin checks; flag tight tokens
// ============================================================================
__global__ __launch_bounds__(256) void gate_margin_kernel(
    const float* __restrict__ bias,
    float* __restrict__ out, int out_size)
{
    const int wid = threadIdx.x >> 5;
    const int l   = threadIdx.x & 31;
    const int t   = blockIdx.x * 8 + wid;

    const float* srow = g_scores + (size_t)t * NEXP;
    float v[8];
#pragma unroll
    for (int k = 0; k < 8; ++k)
        v[k] = srow[k * 32 + l] + bias[k * 32 + l];

    // ---- per-group top-2 sum ----
    float gsc[8];
#pragma unroll
    for (int k = 0; k < 8; ++k) {
        float m1 = v[k];
#pragma unroll
        for (int o = 16; o > 0; o >>= 1) m1 = fmaxf(m1, __shfl_xor_sync(0xffffffffu, m1, o));
        unsigned bal = __ballot_sync(0xffffffffu, v[k] == m1);
        int fl = __ffs(bal) - 1;
        float vx = (l == fl) ? -INFINITY : v[k];
#pragma unroll
        for (int o = 16; o > 0; o >>= 1) vx = fmaxf(vx, __shfl_xor_sync(0xffffffffu, vx, o));
        gsc[k] = m1 + vx;
    }

    // ---- top-4 groups + 5th for margin ----
    unsigned keep = 0;
    float g4 = INFINITY;
#pragma unroll
    for (int r = 0; r < 4; ++r) {
        float best = -INFINITY; int bi = 0;
#pragma unroll
        for (int k = 0; k < 8; ++k) {
            bool tk = !((keep >> k) & 1u) && (gsc[k] > best);
            best = tk ? gsc[k] : best;
            bi   = tk ? k : bi;
        }
        keep |= 1u << bi;
        g4 = best;
    }
    float g5 = -INFINITY;
#pragma unroll
    for (int k = 0; k < 8; ++k)
        if (!((keep >> k) & 1u)) g5 = fmaxf(g5, gsc[k]);

    bool flag = (g4 - g5) < MARG_G;

    float cand[8];
#pragma unroll
    for (int k = 0; k < 8; ++k) cand[k] = ((keep >> k) & 1u) ? v[k] : -INFINITY;

    // ---- extract top-9 (jax tie-break: lower expert idx) ----
    float sval[9]; int sel[9];
#pragma unroll
    for (int r = 0; r < 9; ++r) {
        float bv = cand[0]; int bk = 0;
#pragma unroll
        for (int k = 1; k < 8; ++k) {
            bool tk = cand[k] > bv;
            bv = tk ? cand[k] : bv;
            bk = tk ? k : bk;
        }
        int be = bk * 32 + l;
#pragma unroll
        for (int o = 16; o > 0; o >>= 1) {
            float ov = __shfl_xor_sync(0xffffffffu, bv, o);
            int   oe = __shfl_xor_sync(0xffffffffu, be, o);
            if (ov > bv || (ov == bv && oe < be)) { bv = ov; be = oe; }
        }
        sval[r] = bv; sel[r] = be;
        const int kk = be >> 5, ll = be & 31;
#pragma unroll
        for (int k = 0; k < 8; ++k)
            if (k == kk && l == ll) cand[k] = -INFINITY;
    }
#pragma unroll
    for (int r = 0; r < 8; ++r)
        flag = flag || ((sval[r] - sval[r + 1]) < MARG_T);

    if (l == 0) {
        if (flag) {
            int idx = atomicAdd(&g_nflag, 1);
            g_flags[idx] = t;
        }
        float wv[8], sw = 0.f;
#pragma unroll
        for (int r = 0; r < 8; ++r) { wv[r] = srow[sel[r]]; sw += wv[r]; }
        const float inv = 2.5f / (sw + 1e-20f);
        float4 w0 = make_float4(wv[0] * inv, wv[1] * inv, wv[2] * inv, wv[3] * inv);
        float4 w1 = make_float4(wv[4] * inv, wv[5] * inv, wv[6] * inv, wv[7] * inv);
        float4* wo = (float4*)(out + (size_t)t * 8);
        wo[0] = w0; wo[1] = w1;
        if (out_size >= 2 * T_TOK * 8) {
            float4 i0 = make_float4((float)sel[0], (float)sel[1], (float)sel[2], (float)sel[3]);
            float4 i1 = make_float4((float)sel[4], (float)sel[5], (float)sel[6], (float)sel[7]);
            float4* io = (float4*)(out + (size_t)T_TOK * 8 + (size_t)t * 8);
            io[0] = i0; io[1] = i1;
        }
    }
}

// ============================================================================
// K3: exact serial recompute + gate for flagged tokens
//   (per-element fp32 FMA chain over k ascending — reproduces reference)
// ============================================================================
__global__ __launch_bounds__(256) void fixup_kernel(
    const float* __restrict__ x, const float* __restrict__ w,
    const float* __restrict__ bias,
    float* __restrict__ out, int out_size)
{
    __shared__ float xs[HID];
    __shared__ float ss[NEXP];

    const int tid = threadIdx.x;
    const int nflag = g_nflag;

    for (int fi = blockIdx.x; fi < nflag; fi += gridDim.x) {
        const int t = g_flags[fi];

        for (int i = tid; i < HID; i += 256)
            xs[i] = x[(size_t)t * HID + i];
        __syncthreads();

        // serial ascending-k chain, one expert per thread
        {
            const float4* wr = (const float4*)(w + (size_t)tid * HID);
            float acc = 0.f;
#pragma unroll 8
            for (int q = 0; q < HID / 4; ++q) {
                float4 f = wr[q];
                const float* xq = xs + q * 4;
                acc = fmaf(xq[0], f.x, acc);
                acc = fmaf(xq[1], f.y, acc);
                acc = fmaf(xq[2], f.z, acc);
                acc = fmaf(xq[3], f.w, acc);
            }
            ss[tid] = 1.f / (1.f + expf(-acc));
        }
        __syncthreads();

        if (tid < 32) {
            const int l = tid;
            float v[8];
#pragma unroll
            for (int k = 0; k < 8; ++k)
                v[k] = ss[k * 32 + l] + bias[k * 32 + l];

            float gsc[8];
#pragma unroll
            for (int k = 0; k < 8; ++k) {
                float m1 = v[k];
#pragma unroll
                for (int o = 16; o > 0; o >>= 1) m1 = fmaxf(m1, __shfl_xor_sync(0xffffffffu, m1, o));
                unsigned bal = __ballot_sync(0xffffffffu, v[k] == m1);
                int fl = __ffs(bal) - 1;
                float vx = (l == fl) ? -INFINITY : v[k];
#pragma unroll
                for (int o = 16; o > 0; o >>= 1) vx = fmaxf(vx, __shfl_xor_sync(0xffffffffu, vx, o));
                gsc[k] = m1 + vx;
            }
            unsigned keep = 0;
#pragma unroll
            for (int r = 0; r < 4; ++r) {
                float best = -INFINITY; int bi = 0;
#pragma unroll
                for (int k = 0; k < 8; ++k) {
                    bool tk = !((keep >> k) & 1u) && (gsc[k] > best);
                    best = tk ? gsc[k] : best;
                    bi   = tk ? k : bi;
                }
                keep |= 1u << bi;
            }
            float cand[8];
#pragma unroll
            for (int k = 0; k < 8; ++k) cand[k] = ((keep >> k) & 1u) ? v[k] : -INFINITY;

            int sel[8]; float wv[8];
#pragma unroll
            for (int r = 0; r < 8; ++r) {
                float bv = cand[0]; int bk = 0;
#pragma unroll
                for (int k = 1; k < 8; ++k) {
                    bool tk = cand[k] > bv;
                    bv = tk ? cand[k] : bv;
                    bk = tk ? k : bk;
                }
                int be = bk * 32 + l;
#pragma unroll
                for (int o = 16; o > 0; o >>= 1) {
                    float ov = __shfl_xor_sync(0xffffffffu, bv, o);
                    int   oe = __shfl_xor_sync(0xffffffffu, be, o);
                    if (ov > bv || (ov == bv && oe < be)) { bv = ov; be = oe; }
                }
                sel[r] = be;
                const int kk = be >> 5, ll = be & 31;
#pragma unroll
                for (int k = 0; k < 8; ++k)
                    if (k == kk && l == ll) cand[k] = -INFINITY;
            }
            if (l == 0) {
                float sw = 0.f;
#pragma unroll
                for (int r = 0; r < 8; ++r) { wv[r] = ss[sel[r]]; sw += wv[r]; }
                const float inv = 2.5f / (sw + 1e-20f);
                float* wo = out + (size_t)t * 8;
#pragma unroll
                for (int r = 0; r < 8; ++r) wo[r] = wv[r] * inv;
                if (out_size >= 2 * T_TOK * 8) {
                    float* io = out + (size_t)T_TOK * 8 + (size_t)t * 8;
#pragma unroll
                    for (int r = 0; r < 8; ++r) io[r] = (float)sel[r];
                }
            }
        }
        __syncthreads();
    }
}

// ============================================================================
extern "C" void kernel_launch(void* const* d_in, const int* in_sizes, int n_in,
                              void* d_out, int out_size)
{
    const float* x = nullptr; const float* w = nullptr; const float* b = nullptr;
    for (int i = 0; i < n_in; ++i) {
        long long sz = in_sizes[i];
        if (sz == (long long)T_TOK * HID) x = (const float*)d_in[i];
        else if (sz == (long long)NEXP * HID) w = (const float*)d_in[i];
        else if (sz == NEXP) b = (const float*)d_in[i];
    }
    float* out = (float*)d_out;

    cudaFuncSetAttribute(gemm_f16x2_kernel,
                         cudaFuncAttributeMaxDynamicSharedMemorySize, SMEM_BYTES);

    reset_kernel<<<1, 1>>>();
    gemm_f16x2_kernel<<<(T_TOK / BM) * (NEXP / BN), 256, SMEM_BYTES>>>(x, w);
    gate_margin_kernel<<<T_TOK / 8, 256>>>(b, out, out_size);
    fixup_kernel<<<256, 256>>>(x, w, b, out, out_size);
}